// round 3
// baseline (speedup 1.0000x reference)
#include <cuda_runtime.h>
#include <math.h>
#include <stdint.h>

// ---------------------------------------------------------------------------
// RetinaHead focal + smooth-L1 loss, 4-kernel pipeline:
//   1) rhl_assign : per-anchor IoU argmax -> int8 code, smooth-L1 reg loss
//   2) rhl_focal  : streaming focal-loss reduction over clas  (DRAM-bound)
//   3) rhl_final  : per-image normalization + batch mean -> out[2]
//   4) rhl_reset  : zero accumulators for next graph replay
// ---------------------------------------------------------------------------

#define MAX_B   64
#define MAX_A   1100000
#define TILE    256

__device__ double g_cls[MAX_B];    // zero at module load; rhl_reset re-zeros
__device__ double g_reg[MAX_B];
__device__ int    g_npos[MAX_B];
__device__ int8_t g_code[MAX_A * 8];   // per-anchor code: >=0 class, -1 ignore, -2 neg

// ======================= kernel 1: assignment ==============================
__global__ __launch_bounds__(TILE)
void rhl_assign(const float* __restrict__ anchors,
                const float* __restrict__ targets,
                const float* __restrict__ regs,
                int A, int T)
{
    extern __shared__ char smem_raw[];
    float4* s_box  = (float4*)smem_raw;                                // [T]
    float2* s_meta = (float2*)(smem_raw + sizeof(float4) * (size_t)T); // [T] (label, area)

    __shared__ float s_r[TILE / 32];
    __shared__ int   s_n[TILE / 32];

    const int tid = threadIdx.x;
    const int b   = blockIdx.y;
    const int a   = blockIdx.x * TILE + tid;

    for (int t = tid; t < T; t += TILE) {
        const float* tp = targets + ((size_t)b * T + t) * 5;
        const float x1 = tp[0], y1 = tp[1], x2 = tp[2], y2 = tp[3], lb = tp[4];
        s_box[t]  = make_float4(x1, y1, x2, y2);
        s_meta[t] = make_float2(lb, __fmul_rn(x2 - x1, y2 - y1));
    }
    __syncthreads();

    float regloss = 0.0f;
    int   npos    = 0;

    if (a < A) {
        const float4 ab = ((const float4*)anchors)[a];
        const float ax1 = ab.x, ay1 = ab.y, ax2 = ab.z, ay2 = ab.w;
        const float areaA = __fmul_rn(ax2 - ax1, ay2 - ay1);

        float best = -1.0f;
        int   bestt = 0;
        #pragma unroll 2
        for (int t = 0; t < T; ++t) {
            const float4 tb = s_box[t];
            const float2 tm = s_meta[t];
            const float lx = fmaxf(ax1, tb.x), ly = fmaxf(ay1, tb.y);
            const float rx = fminf(ax2, tb.z), ry = fminf(ay2, tb.w);
            const float w = fmaxf(rx - lx, 0.0f), h = fmaxf(ry - ly, 0.0f);
            const float inter = __fmul_rn(w, h);
            // XLA op order: (area_a + area_b) - inter, IEEE divide
            float iou = inter / ((areaA + tm.y) - inter);
            if (tm.x == -1.0f) iou = -1.0f;
            if (iou > best) { best = iou; bestt = t; }   // first-max argmax
        }

        int code = -1;
        if (best >= 0.5f) {
            code = (int)s_meta[bestt].x;
            npos = 1;
            const float4 tb = s_box[bestt];
            const float pcx = (ax1 + ax2) * 0.5f, pcy = (ay1 + ay2) * 0.5f;
            const float pw  = ax2 - ax1,          ph  = ay2 - ay1;
            const float g0 = ((tb.x + tb.z) * 0.5f - pcx) / (0.1f * pw);
            const float g1 = ((tb.y + tb.w) * 0.5f - pcy) / (0.1f * ph);
            const float g2 = logf((tb.z - tb.x) / pw) / 0.2f;
            const float g3 = logf((tb.w - tb.y) / ph) / 0.2f;
            const float4 rg = ((const float4*)regs)[(size_t)b * A + a];
            const float ge[4] = {g0, g1, g2, g3};
            const float rr[4] = {rg.x, rg.y, rg.z, rg.w};
            #pragma unroll
            for (int k = 0; k < 4; ++k) {
                const float d = fabsf(ge[k] - rr[k]);
                regloss += (d <= (1.0f/9.0f)) ? (4.5f * d) * d
                                              : d - (0.5f/9.0f);
            }
        } else if (best < 0.4f) {
            code = -2;
        }
        g_code[(size_t)b * A + a] = (int8_t)code;
    }

    float rs = regloss; int ns = npos;
    #pragma unroll
    for (int o = 16; o; o >>= 1) {
        rs += __shfl_down_sync(0xffffffffu, rs, o);
        ns += __shfl_down_sync(0xffffffffu, ns, o);
    }
    const int wid = tid >> 5, lane = tid & 31;
    if (lane == 0) { s_r[wid] = rs; s_n[wid] = ns; }
    __syncthreads();
    if (tid == 0) {
        float tr = 0.0f; int tn = 0;
        #pragma unroll
        for (int w = 0; w < TILE / 32; ++w) { tr += s_r[w]; tn += s_n[w]; }
        if (tr != 0.0f) atomicAdd(&g_reg[b], (double)tr);
        if (tn)         atomicAdd(&g_npos[b], tn);
    }
}

// ======================= kernel 2: streaming focal loss ====================
// focal for one float4; ac = anchor code, cl = class idx of v.x
__device__ __forceinline__ float focal4(float4 v, int ac, int cl)
{
    const float LN2 = 0.6931471805599453f;
    const float A1  = 0.25f * LN2;
    const float A0  = 0.75f * LN2;
    const float a0m = (ac == -1) ? 0.0f : A0;   // ignore-mask folded into alpha
    const float a1m = (ac == -1) ? 0.0f : A1;
    float r = 0.0f;
    const float vv[4] = {v.x, v.y, v.z, v.w};
    #pragma unroll
    for (int k = 0; k < 4; ++k) {
        const float c    = fminf(fmaxf(vv[k], 1e-4f), 1.0f - 1e-4f);
        const float om   = 1.0f - c;
        const bool  one  = (ac == cl + k);
        const float s    = one ? om : c;
        const float larg = one ? c  : om;
        const float lg2  = __log2f(larg);
        const float af   = one ? a1m : a0m;
        r = fmaf(-(af * s) * s, lg2, r);
    }
    return r;
}

template<int Q_FIXED>   // Q = C/4 (float4s per anchor), 0 => runtime
__global__ __launch_bounds__(TILE, 4)
void rhl_focal(const float* __restrict__ clas, int A, int Q_rt)
{
    const int Q = (Q_FIXED > 0) ? Q_FIXED : Q_rt;
    const int b = blockIdx.y;
    const float4* __restrict__ cp4 =
        (const float4*)(clas + (size_t)b * A * (size_t)Q * 4);
    const int8_t* __restrict__ codes = g_code + (size_t)b * A;

    const int n4     = A * Q;
    const int stride = gridDim.x * TILE;
    int i = blockIdx.x * TILE + threadIdx.x;

    float acc0 = 0.0f, acc1 = 0.0f, acc2 = 0.0f, acc3 = 0.0f;
    for (; i + 3 * stride < n4; i += 4 * stride) {
        const int i0 = i, i1 = i + stride, i2 = i + 2 * stride, i3 = i + 3 * stride;
        const float4 v0 = __ldcs(cp4 + i0);
        const float4 v1 = __ldcs(cp4 + i1);
        const float4 v2 = __ldcs(cp4 + i2);
        const float4 v3 = __ldcs(cp4 + i3);
        const int a0i = i0 / Q, a1i = i1 / Q, a2i = i2 / Q, a3i = i3 / Q;
        const int c0 = codes[a0i], c1 = codes[a1i], c2 = codes[a2i], c3 = codes[a3i];
        acc0 += focal4(v0, c0, (i0 - a0i * Q) * 4);
        acc1 += focal4(v1, c1, (i1 - a1i * Q) * 4);
        acc2 += focal4(v2, c2, (i2 - a2i * Q) * 4);
        acc3 += focal4(v3, c3, (i3 - a3i * Q) * 4);
    }
    for (; i < n4; i += stride) {
        const int ai = i / Q;
        acc0 += focal4(__ldcs(cp4 + i), codes[ai], (i - ai * Q) * 4);
    }
    float acc = (acc0 + acc1) + (acc2 + acc3);

    __shared__ float s_c[TILE / 32];
    #pragma unroll
    for (int o = 16; o; o >>= 1)
        acc += __shfl_down_sync(0xffffffffu, acc, o);
    const int wid = threadIdx.x >> 5, lane = threadIdx.x & 31;
    if (lane == 0) s_c[wid] = acc;
    __syncthreads();
    if (threadIdx.x == 0) {
        float t = 0.0f;
        #pragma unroll
        for (int w = 0; w < TILE / 32; ++w) t += s_c[w];
        atomicAdd(&g_cls[b], (double)t);
    }
}

// scalar fallback for C not divisible by 4
__global__ __launch_bounds__(TILE, 4)
void rhl_focal_scalar(const float* __restrict__ clas, int A, int C)
{
    const int b = blockIdx.y;
    const float* cp = clas + (size_t)b * A * C;
    const int8_t* codes = g_code + (size_t)b * A;
    const int n = A * C;
    const int stride = gridDim.x * TILE;
    const float LN2 = 0.6931471805599453f;
    float acc = 0.0f;
    for (int i = blockIdx.x * TILE + threadIdx.x; i < n; i += stride) {
        const int al = i / C, clc = i - al * C;
        const int ac = codes[al];
        const float c  = fminf(fmaxf(cp[i], 1e-4f), 1.0f - 1e-4f);
        const float om = 1.0f - c;
        const bool one = (ac == clc);
        const float s    = one ? om : c;
        const float larg = one ? c  : om;
        float af = one ? 0.25f * LN2 : 0.75f * LN2;
        if (ac == -1) af = 0.0f;
        acc = fmaf(-(af * s) * s, __log2f(larg), acc);
    }
    __shared__ float s_c[TILE / 32];
    #pragma unroll
    for (int o = 16; o; o >>= 1)
        acc += __shfl_down_sync(0xffffffffu, acc, o);
    const int wid = threadIdx.x >> 5, lane = threadIdx.x & 31;
    if (lane == 0) s_c[wid] = acc;
    __syncthreads();
    if (threadIdx.x == 0) {
        float t = 0.0f;
        #pragma unroll
        for (int w = 0; w < TILE / 32; ++w) t += s_c[w];
        atomicAdd(&g_cls[b], (double)t);
    }
}

// ======================= kernel 3: finalize ================================
__global__ void rhl_final(const float* __restrict__ targets,
                          float* __restrict__ out, int B, int T)
{
    __shared__ double sh_c[8], sh_r[8];
    const int wid  = threadIdx.x >> 5;
    const int lane = threadIdx.x & 31;

    double cs = 0.0, rs = 0.0;
    for (int b = wid; b < B; b += 8) {
        bool v = false;
        for (int t = lane; t < T; t += 32)
            v |= (targets[((size_t)b * T + t) * 5 + 4] != -1.0f);
        const bool hv = __any_sync(0xffffffffu, v);
        if (lane == 0) {
            const int np = g_npos[b];
            const double npd = (double)np;
            cs += hv ? g_cls[b] / fmax(npd, 1.0) : 0.0;
            rs += (hv && np > 0) ? g_reg[b] / (npd * 4.0) : 0.0;
        }
    }
    if (lane == 0) { sh_c[wid] = cs; sh_r[wid] = rs; }
    __syncthreads();
    if (threadIdx.x == 0) {
        double tc = 0.0, tr = 0.0;
        for (int w = 0; w < 8; ++w) { tc += sh_c[w]; tr += sh_r[w]; }
        out[0] = (float)(tc / (double)B);
        out[1] = (float)(tr / (double)B);
    }
}

// ======================= kernel 4: reset (for next replay) =================
__global__ void rhl_reset() {
    int i = threadIdx.x;
    if (i < MAX_B) { g_cls[i] = 0.0; g_reg[i] = 0.0; g_npos[i] = 0; }
}

// ===========================================================================
extern "C" void kernel_launch(void* const* d_in, const int* in_sizes, int n_in,
                              void* d_out, int out_size)
{
    const float* clas    = (const float*)d_in[0];
    const float* regs    = (const float*)d_in[1];
    const float* anchors = (const float*)d_in[2];
    const float* targets = (const float*)d_in[3];
    float* out = (float*)d_out;

    const int A = in_sizes[2] / 4;                 // anchors [1,A,4]
    const int B = in_sizes[1] / (A * 4);           // regs [B,A,4]
    const int C = in_sizes[0] / (B * A);           // clas [B,A,C]
    const int T = in_sizes[3] / (B * 5);           // targets [B,T,5]

    // 1) assignment
    {
        dim3 grid((A + TILE - 1) / TILE, B);
        const size_t smem = (sizeof(float4) + sizeof(float2)) * (size_t)T;
        rhl_assign<<<grid, TILE, smem>>>(anchors, targets, regs, A, T);
    }
    // 2) focal streaming reduction
    {
        dim3 grid(148, B);
        if (C == 80)            rhl_focal<20><<<grid, TILE>>>(clas, A, 20);
        else if ((C & 3) == 0)  rhl_focal<0><<<grid, TILE>>>(clas, A, C / 4);
        else                    rhl_focal_scalar<<<grid, TILE>>>(clas, A, C);
    }
    // 3) finalize, 4) reset accumulators
    rhl_final<<<1, 256>>>(targets, out, B, T);
    rhl_reset<<<1, MAX_B>>>();
}